// round 1
// baseline (speedup 1.0000x reference)
#include <cuda_runtime.h>
#include <cuda_bf16.h>

// Problem constants (fixed shapes)
#define NTOK  4096      // B*S = 2*2048
#define DDIM  1024
#define WDIM  4096
#define SLOT  8
#define NLEAF 8         // 1 << TREE_DEPTH
#define NC    11        // SLOT + 3

// Scratch (static device allocations — allowed; runtime alloc is not)
__device__ float g_wsel [WDIM * NLEAF * 9];          // per (w,leaf): 8 weights + 1 bias
__device__ float g_slots[NTOK * SLOT];               // tanh(hidden @ slot_w + b)
__device__ float g_roots[(size_t)NTOK * WDIM];       // 64 MB

// Accurate-enough fast tanh: tanh(x) = 1 - 2/(exp(2x)+1).
// __expf -> MUFU ex2 (~2 ulp), __fdividef -> MUFU rcp. Handles +/-inf saturation correctly.
__device__ __forceinline__ float tanh_fast(float x) {
    float e = __expf(2.0f * x);
    return 1.0f - __fdividef(2.0f, e + 1.0f);
}

// ---------------------------------------------------------------------------
// Kernel 1: selector softmax + fold constants.
// For each (w, leaf): softmax over 11 logits; keep 8 slot weights and
// bias = sel[10]*(+1) + sel[9]*0 + sel[8]*(-1).
// ---------------------------------------------------------------------------
__global__ __launch_bounds__(256)
void prep_selector_kernel(const float* __restrict__ leaf_logits,
                          float* __restrict__ wsel) {
    int idx = blockIdx.x * blockDim.x + threadIdx.x;   // w*8 + leaf
    if (idx >= WDIM * NLEAF) return;
    const float* lg = leaf_logits + (size_t)idx * NC;

    float m = lg[0];
    #pragma unroll
    for (int c = 1; c < NC; c++) m = fmaxf(m, lg[c]);

    float e[NC];
    float s = 0.0f;
    #pragma unroll
    for (int c = 0; c < NC; c++) { e[c] = __expf(lg[c] - m); s += e[c]; }
    float inv = 1.0f / s;

    float* o = wsel + (size_t)idx * 9;
    #pragma unroll
    for (int c = 0; c < SLOT; c++) o[c] = e[c] * inv;
    o[8] = (e[10] - e[8]) * inv;   // folded constants [-1, 0, 1]
}

// ---------------------------------------------------------------------------
// Kernel 2: slots = tanh(hidden @ slot_w + slot_b).  One warp per token.
// ---------------------------------------------------------------------------
__global__ __launch_bounds__(256)
void slots_kernel(const float* __restrict__ hidden,
                  const float* __restrict__ slot_w,
                  const float* __restrict__ slot_b,
                  float* __restrict__ slots) {
    int warp = (blockIdx.x * blockDim.x + threadIdx.x) >> 5;
    int lane = threadIdx.x & 31;
    if (warp >= NTOK) return;

    const float* h = hidden + (size_t)warp * DDIM;
    float acc[SLOT];
    #pragma unroll
    for (int s = 0; s < SLOT; s++) acc[s] = 0.0f;

    for (int j = lane; j < DDIM; j += 32) {
        float hv = h[j];
        float4 w0 = *reinterpret_cast<const float4*>(slot_w + (size_t)j * SLOT);
        float4 w1 = *reinterpret_cast<const float4*>(slot_w + (size_t)j * SLOT + 4);
        acc[0] = fmaf(hv, w0.x, acc[0]);
        acc[1] = fmaf(hv, w0.y, acc[1]);
        acc[2] = fmaf(hv, w0.z, acc[2]);
        acc[3] = fmaf(hv, w0.w, acc[3]);
        acc[4] = fmaf(hv, w1.x, acc[4]);
        acc[5] = fmaf(hv, w1.y, acc[5]);
        acc[6] = fmaf(hv, w1.z, acc[6]);
        acc[7] = fmaf(hv, w1.w, acc[7]);
    }
    #pragma unroll
    for (int off = 16; off > 0; off >>= 1) {
        #pragma unroll
        for (int s = 0; s < SLOT; s++)
            acc[s] += __shfl_down_sync(0xffffffffu, acc[s], off);
    }
    if (lane == 0) {
        #pragma unroll
        for (int s = 0; s < SLOT; s++)
            slots[(size_t)warp * SLOT + s] = tanh_fast(acc[s] + slot_b[s]);
    }
}

// ---------------------------------------------------------------------------
// Kernel 3: roots[t, w] = tree( values[t, w, 0..7] )
// values[t,w,l] = dot(wsel[w,l,0:8], slots[t,:]) + wsel[w,l,8]
// Tile 32 tokens x 32 w per CTA; 256 threads, 4 (t,w) pairs each.
// ---------------------------------------------------------------------------
__global__ __launch_bounds__(256)
void roots_kernel(const float* __restrict__ wsel,
                  const float* __restrict__ slots,
                  const float* __restrict__ np,   // node_params[5]
                  float* __restrict__ roots) {
    const int BT = 32, BW = 32;
    __shared__ float s_slots[BT][SLOT];
    __shared__ float s_wsel[BW][73];   // 72 used, padded (73 coprime w/ 32 banks)

    int tid = threadIdx.x;
    int t0 = blockIdx.y * BT;
    int w0 = blockIdx.x * BW;

    // load wsel tile (32 * 72 floats, contiguous in global)
    for (int i = tid; i < BW * 72; i += 256) {
        int r = i / 72, c = i % 72;
        s_wsel[r][c] = wsel[(size_t)(w0 + r) * 72 + c];
    }
    // load slots tile (32 * 8 floats)
    if (tid < BT * SLOT) {
        int r = tid / SLOT, c = tid % SLOT;
        s_slots[r][c] = slots[(size_t)(t0 + r) * SLOT + c];
    }
    __syncthreads();

    float lw = np[0], rw = np[1], pw = np[2], dw = np[3], nb = np[4];

    int tx = tid & 31;        // w within tile
    int ty = tid >> 5;        // 0..7
    #pragma unroll
    for (int i = 0; i < 4; i++) {
        int tl = ty * 4 + i;  // token within tile
        float v[NLEAF];
        #pragma unroll
        for (int l = 0; l < NLEAF; l++) {
            const float* wv = &s_wsel[tx][l * 9];
            float a = wv[8];
            #pragma unroll
            for (int c = 0; c < SLOT; c++)
                a = fmaf(wv[c], s_slots[tl][c], a);
            v[l] = a;
        }
        // 3-level tree reduce (in-place, ascending j is safe)
        #pragma unroll
        for (int n = 4; n >= 1; n >>= 1) {
            #pragma unroll
            for (int j = 0; j < 4; j++) {
                if (j < n) {
                    float L = v[2 * j], R = v[2 * j + 1];
                    float z = fmaf(lw, L, nb);
                    z = fmaf(rw, R, z);
                    z = fmaf(pw * L, R, z);
                    z = fmaf(dw, L - R, z);
                    v[j] = tanh_fast(z);
                }
            }
        }
        roots[(size_t)(t0 + tl) * WDIM + w0 + tx] = v[0];
    }
}

// ---------------------------------------------------------------------------
// Kernel 4: out = roots @ out_w + out_b.   M=4096, N=1024, K=4096, fp32.
// 128x128 block tile, BK=16, 256 threads, 8x8 microtile, float4 everywhere.
// ---------------------------------------------------------------------------
__global__ __launch_bounds__(256)
void gemm_kernel(const float* __restrict__ A,     // [M, K] = roots
                 const float* __restrict__ B,     // [K, N] = out_w
                 const float* __restrict__ bias,  // [N]    = out_b
                 float* __restrict__ C) {         // [M, N]
    const int M = NTOK, N = DDIM, K = WDIM;
    const int BK = 16;
    __shared__ float As[BK][128];   // stored transposed: As[k][m]
    __shared__ float Bs[BK][128];

    int tid  = threadIdx.x;
    int brow = blockIdx.y * 128;
    int bcol = blockIdx.x * 128;
    int tx = tid & 15;     // 0..15 -> 8 cols each
    int ty = tid >> 4;     // 0..15 -> 8 rows each

    int aRow = tid >> 2;          // 0..63 (and +64)
    int aCol = (tid & 3) * 4;     // 0,4,8,12
    int bRow = tid >> 5;          // 0..7 (and +8)
    int bCol = (tid & 31) * 4;

    const float* Ap = A + (size_t)brow * K;
    const float* Bp = B + bcol;

    float acc[8][8];
    #pragma unroll
    for (int i = 0; i < 8; i++)
        #pragma unroll
        for (int j = 0; j < 8; j++) acc[i][j] = 0.0f;

    for (int k0 = 0; k0 < K; k0 += BK) {
        float4 a0 = *reinterpret_cast<const float4*>(Ap + (size_t)aRow * K + k0 + aCol);
        float4 a1 = *reinterpret_cast<const float4*>(Ap + (size_t)(aRow + 64) * K + k0 + aCol);
        As[aCol + 0][aRow] = a0.x;
        As[aCol + 1][aRow] = a0.y;
        As[aCol + 2][aRow] = a0.z;
        As[aCol + 3][aRow] = a0.w;
        As[aCol + 0][aRow + 64] = a1.x;
        As[aCol + 1][aRow + 64] = a1.y;
        As[aCol + 2][aRow + 64] = a1.z;
        As[aCol + 3][aRow + 64] = a1.w;
        float4 b0 = *reinterpret_cast<const float4*>(Bp + (size_t)(k0 + bRow) * N + bCol);
        float4 b1 = *reinterpret_cast<const float4*>(Bp + (size_t)(k0 + bRow + 8) * N + bCol);
        *reinterpret_cast<float4*>(&Bs[bRow][bCol])     = b0;
        *reinterpret_cast<float4*>(&Bs[bRow + 8][bCol]) = b1;
        __syncthreads();

        #pragma unroll
        for (int k = 0; k < BK; k++) {
            float ar[8], br[8];
            *reinterpret_cast<float4*>(&ar[0]) = *reinterpret_cast<float4*>(&As[k][ty * 8]);
            *reinterpret_cast<float4*>(&ar[4]) = *reinterpret_cast<float4*>(&As[k][ty * 8 + 4]);
            *reinterpret_cast<float4*>(&br[0]) = *reinterpret_cast<float4*>(&Bs[k][tx * 8]);
            *reinterpret_cast<float4*>(&br[4]) = *reinterpret_cast<float4*>(&Bs[k][tx * 8 + 4]);
            #pragma unroll
            for (int i = 0; i < 8; i++)
                #pragma unroll
                for (int j = 0; j < 8; j++)
                    acc[i][j] = fmaf(ar[i], br[j], acc[i][j]);
        }
        __syncthreads();
    }

    #pragma unroll
    for (int i = 0; i < 8; i++) {
        int r = brow + ty * 8 + i;
        #pragma unroll
        for (int j = 0; j < 8; j += 4) {
            int c = bcol + tx * 8 + j;
            float4 o;
            o.x = acc[i][j + 0] + bias[c + 0];
            o.y = acc[i][j + 1] + bias[c + 1];
            o.z = acc[i][j + 2] + bias[c + 2];
            o.w = acc[i][j + 3] + bias[c + 3];
            *reinterpret_cast<float4*>(C + (size_t)r * N + c) = o;
        }
    }
}

// ---------------------------------------------------------------------------
// Launch
// Inputs (metadata order): hidden, slot_w, slot_b, leaf_logits, node_params,
//                          out_w, out_b
// ---------------------------------------------------------------------------
extern "C" void kernel_launch(void* const* d_in, const int* in_sizes, int n_in,
                              void* d_out, int out_size) {
    const float* hidden      = (const float*)d_in[0];
    const float* slot_w      = (const float*)d_in[1];
    const float* slot_b      = (const float*)d_in[2];
    const float* leaf_logits = (const float*)d_in[3];
    const float* node_params = (const float*)d_in[4];
    const float* out_w       = (const float*)d_in[5];
    const float* out_b       = (const float*)d_in[6];
    float* out = (float*)d_out;

    float* wsel;  cudaGetSymbolAddress((void**)&wsel,  g_wsel);
    float* slots; cudaGetSymbolAddress((void**)&slots, g_slots);
    float* roots; cudaGetSymbolAddress((void**)&roots, g_roots);

    // 1) selector softmax + constant folding
    prep_selector_kernel<<<(WDIM * NLEAF + 255) / 256, 256>>>(leaf_logits, wsel);

    // 2) slots (one warp per token)
    slots_kernel<<<(NTOK * 32 + 255) / 256, 256>>>(hidden, slot_w, slot_b, slots);

    // 3) roots: 32x32 tiles over (w, token)
    {
        dim3 grid(WDIM / 32, NTOK / 32);
        roots_kernel<<<grid, 256>>>(wsel, slots, node_params, roots);
    }

    // 4) final GEMM + bias
    {
        dim3 grid(DDIM / 128, NTOK / 128);
        gemm_kernel<<<grid, 256>>>(roots, out_w, out_b, out);
    }
}

// round 3
// speedup vs baseline: 2.1447x; 2.1447x over previous
#include <cuda_runtime.h>
#include <cuda_bf16.h>
#include <cstdint>

// Problem constants (fixed shapes)
#define NTOK  4096      // B*S = 2*2048
#define DDIM  1024
#define WDIM  4096
#define SLOT  8
#define NLEAF 8         // 1 << TREE_DEPTH
#define NC    11        // SLOT + 3

// GEMM tiling: CTA 128(M) x 256(N), K-chunk 64, 512 threads (16 warps, 4x4)
#define TMM 128
#define TNN 256
#define KCC 64
#define GT  512
#define ABYTES (TMM * 128)            // 16 KB  (128 rows x 128B)
#define BBYTES (TNN * 128)            // 32 KB
#define OFF_AH 0
#define OFF_AL (ABYTES)
#define OFF_BH (2 * ABYTES)
#define OFF_BL (2 * ABYTES + BBYTES)
#define STAGE  (2 * ABYTES + 2 * BBYTES)      // 98304
#define GSMEM  (2 * STAGE)                    // 196608
#define NCH    (WDIM / KCC)                   // 64

// Scratch (static device arrays — runtime alloc is forbidden)
__device__ __align__(128) float         g_wsel [WDIM * NLEAF * 9];
__device__ __align__(128) float         g_slots[NTOK * SLOT];
__device__ __align__(128) __nv_bfloat16 g_ah[(size_t)NTOK * WDIM];   // roots hi
__device__ __align__(128) __nv_bfloat16 g_al[(size_t)NTOK * WDIM];   // roots lo
__device__ __align__(128) __nv_bfloat16 g_bh[(size_t)DDIM * WDIM];   // out_w^T hi [N][K]
__device__ __align__(128) __nv_bfloat16 g_bl[(size_t)DDIM * WDIM];   // out_w^T lo

// ---------------------------------------------------------------------------
// PTX helpers (sm_80-era features only — no 'a'-suffix instructions)
// ---------------------------------------------------------------------------
__device__ __forceinline__ uint32_t smem_u32(const void* p) {
    uint32_t a;
    asm("{ .reg .u64 t; cvta.to.shared.u64 t, %1; cvt.u32.u64 %0, t; }"
        : "=r"(a) : "l"(p));
    return a;
}

__device__ __forceinline__ void cp16(uint32_t saddr, const void* g) {
    asm volatile("cp.async.cg.shared.global [%0], [%1], 16;"
                 :: "r"(saddr), "l"(g) : "memory");
}
#define CP_COMMIT() asm volatile("cp.async.commit_group;" ::: "memory")
#define CP_WAIT(n)  asm volatile("cp.async.wait_group %0;" :: "n"(n) : "memory")

__device__ __forceinline__ void ldsm_x4(uint32_t* r, uint32_t addr) {
    asm volatile("ldmatrix.sync.aligned.m8n8.x4.shared.b16 {%0,%1,%2,%3}, [%4];"
                 : "=r"(r[0]), "=r"(r[1]), "=r"(r[2]), "=r"(r[3]) : "r"(addr));
}

__device__ __forceinline__ void mma_bf16(float* c, const uint32_t* a,
                                         uint32_t b0, uint32_t b1) {
    asm volatile(
        "mma.sync.aligned.m16n8k16.row.col.f32.bf16.bf16.f32 "
        "{%0,%1,%2,%3}, {%4,%5,%6,%7}, {%8,%9}, {%0,%1,%2,%3};"
        : "+f"(c[0]), "+f"(c[1]), "+f"(c[2]), "+f"(c[3])
        : "r"(a[0]), "r"(a[1]), "r"(a[2]), "r"(a[3]), "r"(b0), "r"(b1));
}

// Accurate fast tanh: tanh(x) = 1 - 2/(exp(2x)+1)
__device__ __forceinline__ float tanh_fast(float x) {
    float e = __expf(2.0f * x);
    return 1.0f - __fdividef(2.0f, e + 1.0f);
}

// ---------------------------------------------------------------------------
// Kernel 1: selector softmax + constant folding
// ---------------------------------------------------------------------------
__global__ __launch_bounds__(256)
void prep_selector_kernel(const float* __restrict__ leaf_logits,
                          float* __restrict__ wsel) {
    int idx = blockIdx.x * blockDim.x + threadIdx.x;   // w*8 + leaf
    if (idx >= WDIM * NLEAF) return;
    const float* lg = leaf_logits + (size_t)idx * NC;

    float m = lg[0];
    #pragma unroll
    for (int c = 1; c < NC; c++) m = fmaxf(m, lg[c]);

    float e[NC];
    float s = 0.0f;
    #pragma unroll
    for (int c = 0; c < NC; c++) { e[c] = __expf(lg[c] - m); s += e[c]; }
    float inv = 1.0f / s;

    float* o = wsel + (size_t)idx * 9;
    #pragma unroll
    for (int c = 0; c < SLOT; c++) o[c] = e[c] * inv;
    o[8] = (e[10] - e[8]) * inv;   // folded constants [-1, 0, 1]
}

// ---------------------------------------------------------------------------
// Kernel 2: slots = tanh(hidden @ slot_w + slot_b).  One warp per token.
// ---------------------------------------------------------------------------
__global__ __launch_bounds__(256)
void slots_kernel(const float* __restrict__ hidden,
                  const float* __restrict__ slot_w,
                  const float* __restrict__ slot_b,
                  float* __restrict__ slots) {
    int warp = (blockIdx.x * blockDim.x + threadIdx.x) >> 5;
    int lane = threadIdx.x & 31;
    if (warp >= NTOK) return;

    const float* h = hidden + (size_t)warp * DDIM;
    float acc[SLOT];
    #pragma unroll
    for (int s = 0; s < SLOT; s++) acc[s] = 0.0f;

    for (int j = lane; j < DDIM; j += 32) {
        float hv = h[j];
        float4 w0 = *reinterpret_cast<const float4*>(slot_w + (size_t)j * SLOT);
        float4 w1 = *reinterpret_cast<const float4*>(slot_w + (size_t)j * SLOT + 4);
        acc[0] = fmaf(hv, w0.x, acc[0]);
        acc[1] = fmaf(hv, w0.y, acc[1]);
        acc[2] = fmaf(hv, w0.z, acc[2]);
        acc[3] = fmaf(hv, w0.w, acc[3]);
        acc[4] = fmaf(hv, w1.x, acc[4]);
        acc[5] = fmaf(hv, w1.y, acc[5]);
        acc[6] = fmaf(hv, w1.z, acc[6]);
        acc[7] = fmaf(hv, w1.w, acc[7]);
    }
    #pragma unroll
    for (int off = 16; off > 0; off >>= 1) {
        #pragma unroll
        for (int s = 0; s < SLOT; s++)
            acc[s] += __shfl_down_sync(0xffffffffu, acc[s], off);
    }
    if (lane == 0) {
        #pragma unroll
        for (int s = 0; s < SLOT; s++)
            slots[(size_t)warp * SLOT + s] = tanh_fast(acc[s] + slot_b[s]);
    }
}

// ---------------------------------------------------------------------------
// Kernel 3: roots -> bf16 hi/lo split, [token][w] = [M][K] row-major
// ---------------------------------------------------------------------------
__global__ __launch_bounds__(256)
void roots_kernel(const float* __restrict__ wsel,
                  const float* __restrict__ slots,
                  const float* __restrict__ np,
                  __nv_bfloat16* __restrict__ ah,
                  __nv_bfloat16* __restrict__ al) {
    const int BT = 32, BW = 32;
    __shared__ float s_slots[BT][SLOT];
    __shared__ float s_wsel[BW][73];

    int tid = threadIdx.x;
    int t0 = blockIdx.y * BT;
    int w0 = blockIdx.x * BW;

    for (int i = tid; i < BW * 72; i += 256) {
        int r = i / 72, c = i % 72;
        s_wsel[r][c] = wsel[(size_t)(w0 + r) * 72 + c];
    }
    if (tid < BT * SLOT) {
        int r = tid / SLOT, c = tid % SLOT;
        s_slots[r][c] = slots[(size_t)(t0 + r) * SLOT + c];
    }
    __syncthreads();

    float lw = np[0], rw = np[1], pw = np[2], dw = np[3], nb = np[4];

    int tx = tid & 31;
    int ty = tid >> 5;
    #pragma unroll
    for (int i = 0; i < 4; i++) {
        int tl = ty * 4 + i;
        float v[NLEAF];
        #pragma unroll
        for (int l = 0; l < NLEAF; l++) {
            const float* wv = &s_wsel[tx][l * 9];
            float a = wv[8];
            #pragma unroll
            for (int c = 0; c < SLOT; c++)
                a = fmaf(wv[c], s_slots[tl][c], a);
            v[l] = a;
        }
        #pragma unroll
        for (int n = 4; n >= 1; n >>= 1) {
            #pragma unroll
            for (int j = 0; j < 4; j++) {
                if (j < n) {
                    float L = v[2 * j], R = v[2 * j + 1];
                    float z = fmaf(lw, L, nb);
                    z = fmaf(rw, R, z);
                    z = fmaf(pw * L, R, z);
                    z = fmaf(dw, L - R, z);
                    v[j] = tanh_fast(z);
                }
            }
        }
        size_t idx = (size_t)(t0 + tl) * WDIM + w0 + tx;
        __nv_bfloat16 h = __float2bfloat16(v[0]);
        float hf = __bfloat162float(h);
        ah[idx] = h;
        al[idx] = __float2bfloat16(v[0] - hf);
    }
}

// ---------------------------------------------------------------------------
// Kernel 3b: transpose+split out_w [K][N] fp32 -> Bh/Bl [N][K] bf16
// ---------------------------------------------------------------------------
__global__ __launch_bounds__(256)
void transpose_split_kernel(const float* __restrict__ W,
                            __nv_bfloat16* __restrict__ bh,
                            __nv_bfloat16* __restrict__ bl) {
    __shared__ float t[32][33];
    int tx = threadIdx.x, ty = threadIdx.y;       // block (32, 8)
    int k0 = blockIdx.x * 32, n0 = blockIdx.y * 32;

    #pragma unroll
    for (int i = 0; i < 4; i++)
        t[ty + 8 * i][tx] = W[(size_t)(k0 + ty + 8 * i) * DDIM + n0 + tx];
    __syncthreads();

    #pragma unroll
    for (int i = 0; i < 4; i++) {
        float v = t[tx][ty + 8 * i];
        __nv_bfloat16 h = __float2bfloat16(v);
        float hf = __bfloat162float(h);
        size_t o = (size_t)(n0 + ty + 8 * i) * WDIM + k0 + tx;
        bh[o] = h;
        bl[o] = __float2bfloat16(v - hf);
    }
}

// ---------------------------------------------------------------------------
// Kernel 4: mma.sync bf16 GEMM.  C[4096,1024] = (Ah+Al)(Bh+Bl)^T + bias
// 3 passes (AhBh + AlBh + AhBl) accumulated in fp32 mma accumulators.
// ---------------------------------------------------------------------------
__global__ void __launch_bounds__(GT, 1)
gemm_mma_kernel(const __nv_bfloat16* __restrict__ Ah,
                const __nv_bfloat16* __restrict__ Al,
                const __nv_bfloat16* __restrict__ Bh,
                const __nv_bfloat16* __restrict__ Bl,
                const float* __restrict__ bias,
                float* __restrict__ C) {
    extern __shared__ char smem[];
    const uint32_t sbase = smem_u32(smem);
    const int tid  = threadIdx.x;
    const int lane = tid & 31;
    const int w    = tid >> 5;        // 0..15
    const int wm   = w & 3;           // M warp coord (x32)
    const int wn   = w >> 2;          // N warp coord (x64)
    const int brow = blockIdx.y * TMM;
    const int bcol = blockIdx.x * TNN;
    const int K = WDIM;

    float acc[2][8][4];
    #pragma unroll
    for (int a = 0; a < 2; a++)
        #pragma unroll
        for (int b = 0; b < 8; b++)
            #pragma unroll
            for (int c = 0; c < 4; c++) acc[a][b][c] = 0.0f;

    // ldmatrix lane->address precomputation
    const int lr   = lane & 7;
    const int ls8  = (lane >> 3) & 1;       // A: +8 rows    B: +1 chunk
    const int lhi  = lane >> 4;             // A: +1 chunk   B: +8 rows
    const int arow0 = wm * 32 + lr + ls8 * 8;
    const int brow0 = wn * 64 + lr + lhi * 8;
    const uint32_t aswz = arow0 & 7;
    const uint32_t bswz = brow0 & 7;
    uint32_t arowb[2], browb[4];
    #pragma unroll
    for (int mt = 0; mt < 2; mt++) arowb[mt] = (uint32_t)(arow0 + mt * 16) << 7;
    #pragma unroll
    for (int i = 0; i < 4; i++)    browb[i] = (uint32_t)(brow0 + i * 16) << 7;

    // stage loader: A rows (brow..brow+127), B rows (bcol..bcol+255), k0..k0+63
    auto load_stage = [&](int ci, int buf) {
        const uint32_t sb = sbase + buf * STAGE;
        const int k0 = ci * KCC;
        #pragma unroll
        for (int it = 0; it < 2; it++) {
            int idx = tid + it * GT;          // 0..1023
            int r = idx >> 3, c = idx & 7;
            uint32_t sw = ((uint32_t)r << 7) + (((uint32_t)(c ^ (r & 7))) << 4);
            size_t g = (size_t)(brow + r) * K + k0 + c * 8;
            cp16(sb + OFF_AH + sw, Ah + g);
            cp16(sb + OFF_AL + sw, Al + g);
        }
        #pragma unroll
        for (int it = 0; it < 4; it++) {
            int idx = tid + it * GT;          // 0..2047
            int r = idx >> 3, c = idx & 7;
            uint32_t sw = ((uint32_t)r << 7) + (((uint32_t)(c ^ (r & 7))) << 4);
            size_t g = (size_t)(bcol + r) * K + k0 + c * 8;
            cp16(sb + OFF_BH + sw, Bh + g);
            cp16(sb + OFF_BL + sw, Bl + g);
        }
    };

    load_stage(0, 0);
    CP_COMMIT();

    for (int i = 0; i < NCH; i++) {
        if (i + 1 < NCH) {
            load_stage(i + 1, (i + 1) & 1);
            CP_COMMIT();
            CP_WAIT(1);
        } else {
            CP_WAIT(0);
        }
        __syncthreads();

        const uint32_t sb = sbase + (i & 1) * STAGE;
        #pragma unroll
        for (int s = 0; s < 4; s++) {
            uint32_t ach = (((uint32_t)(2 * s + lhi)) ^ aswz) << 4;
            uint32_t bch = (((uint32_t)(2 * s + ls8)) ^ bswz) << 4;
            uint32_t afh[2][4], afl[2][4], bf[4][4];
            #pragma unroll
            for (int mt = 0; mt < 2; mt++) {
                ldsm_x4(afh[mt], sb + OFF_AH + arowb[mt] + ach);
                ldsm_x4(afl[mt], sb + OFF_AL + arowb[mt] + ach);
            }
            #pragma unroll
            for (int bt = 0; bt < 4; bt++)
                ldsm_x4(bf[bt], sb + OFF_BH + browb[bt] + bch);
            // passes hh + lh
            #pragma unroll
            for (int mt = 0; mt < 2; mt++)
                #pragma unroll
                for (int bt = 0; bt < 4; bt++) {
                    mma_bf16(acc[mt][2 * bt + 0], afh[mt], bf[bt][0], bf[bt][1]);
                    mma_bf16(acc[mt][2 * bt + 1], afh[mt], bf[bt][2], bf[bt][3]);
                    mma_bf16(acc[mt][2 * bt + 0], afl[mt], bf[bt][0], bf[bt][1]);
                    mma_bf16(acc[mt][2 * bt + 1], afl[mt], bf[bt][2], bf[bt][3]);
                }
            // pass hl (reuse bf regs)
            #pragma unroll
            for (int bt = 0; bt < 4; bt++)
                ldsm_x4(bf[bt], sb + OFF_BL + browb[bt] + bch);
            #pragma unroll
            for (int mt = 0; mt < 2; mt++)
                #pragma unroll
                for (int bt = 0; bt < 4; bt++) {
                    mma_bf16(acc[mt][2 * bt + 0], afh[mt], bf[bt][0], bf[bt][1]);
                    mma_bf16(acc[mt][2 * bt + 1], afh[mt], bf[bt][2], bf[bt][3]);
                }
        }
        __syncthreads();
    }

    // Epilogue: acc -> C + bias
    const int r0 = lane >> 2;
    const int c0 = (lane & 3) * 2;
    #pragma unroll
    for (int mt = 0; mt < 2; mt++) {
        int grow = brow + wm * 32 + mt * 16 + r0;
        #pragma unroll
        for (int half = 0; half < 2; half++) {
            float* crow = C + (size_t)(grow + half * 8) * DDIM;
            #pragma unroll
            for (int nt = 0; nt < 8; nt++) {
                int gc = bcol + wn * 64 + nt * 8 + c0;
                float2 o;
                o.x = acc[mt][nt][half * 2 + 0] + bias[gc];
                o.y = acc[mt][nt][half * 2 + 1] + bias[gc + 1];
                *reinterpret_cast<float2*>(crow + gc) = o;
            }
        }
    }
}

// ---------------------------------------------------------------------------
// Launch.  Inputs: hidden, slot_w, slot_b, leaf_logits, node_params, out_w, out_b
// ---------------------------------------------------------------------------
extern "C" void kernel_launch(void* const* d_in, const int* in_sizes, int n_in,
                              void* d_out, int out_size) {
    const float* hidden      = (const float*)d_in[0];
    const float* slot_w      = (const float*)d_in[1];
    const float* slot_b      = (const float*)d_in[2];
    const float* leaf_logits = (const float*)d_in[3];
    const float* node_params = (const float*)d_in[4];
    const float* out_w       = (const float*)d_in[5];
    const float* out_b       = (const float*)d_in[6];
    float* out = (float*)d_out;

    float* wsel;  cudaGetSymbolAddress((void**)&wsel,  g_wsel);
    float* slots; cudaGetSymbolAddress((void**)&slots, g_slots);
    __nv_bfloat16 *ah, *al, *bh, *bl;
    cudaGetSymbolAddress((void**)&ah, g_ah);
    cudaGetSymbolAddress((void**)&al, g_al);
    cudaGetSymbolAddress((void**)&bh, g_bh);
    cudaGetSymbolAddress((void**)&bl, g_bl);

    cudaFuncSetAttribute(gemm_mma_kernel,
                         cudaFuncAttributeMaxDynamicSharedMemorySize, GSMEM);

    // 1) selector softmax + constant folding
    prep_selector_kernel<<<(WDIM * NLEAF + 255) / 256, 256>>>(leaf_logits, wsel);

    // 2) slots
    slots_kernel<<<(NTOK * 32 + 255) / 256, 256>>>(hidden, slot_b ? hidden : hidden, slot_b, slots);

    // (fix: correct argument order)
    slots_kernel<<<(NTOK * 32 + 255) / 256, 256>>>(hidden, slot_w, slot_b, slots);

    // 3b) transpose + bf16-split out_w
    {
        dim3 grid(WDIM / 32, DDIM / 32);
        transpose_split_kernel<<<grid, dim3(32, 8)>>>(out_w, bh, bl);
    }

    // 3) roots -> bf16 hi/lo
    {
        dim3 grid(WDIM / 32, NTOK / 32);
        roots_kernel<<<grid, 256>>>(wsel, slots, node_params, ah, al);
    }

    // 4) tensor-core GEMM + bias
    {
        dim3 grid(DDIM / TNN, NTOK / TMM);
        gemm_mma_kernel<<<grid, GT, GSMEM>>>(ah, al, bh, bl, out_b, out);
    }
}

// round 4
// speedup vs baseline: 3.5039x; 1.6338x over previous
#include <cuda_runtime.h>
#include <cuda_bf16.h>
#include <cuda_fp16.h>
#include <cstdint>

// Problem constants (fixed shapes)
#define NTOK  4096      // B*S = 2*2048
#define DDIM  1024
#define WDIM  4096
#define SLOT  8
#define NLEAF 8         // 1 << TREE_DEPTH
#define NC    11        // SLOT + 3

// GEMM tiling: CTA 128(M) x 256(N), K-chunk 64, 512 threads (16 warps, 4x4)
#define TMM 128
#define TNN 256
#define KCC 64
#define GT  512
#define ABYTES (TMM * 128)            // 16 KB  (128 rows x 128B)
#define BBYTES (TNN * 128)            // 32 KB
#define OFF_A  0
#define OFF_B  (ABYTES)
#define STAGE  (ABYTES + BBYTES)      // 49152
#define NSTG   3
#define GSMEM  (NSTG * STAGE)         // 147456
#define NCH    (WDIM / KCC)           // 64

// Scratch (static device arrays — runtime alloc is forbidden)
__device__ __align__(128) float  g_wsel [WDIM * NLEAF * 9];
__device__ __align__(128) float  g_slots[NTOK * SLOT];
__device__ __align__(128) __half g_a[(size_t)NTOK * WDIM];   // roots, fp16, [M][K]
__device__ __align__(128) __half g_b[(size_t)DDIM * WDIM];   // out_w^T, fp16, [N][K]

// ---------------------------------------------------------------------------
// PTX helpers (sm_80-era features only — no 'a'-suffix instructions)
// ---------------------------------------------------------------------------
__device__ __forceinline__ uint32_t smem_u32(const void* p) {
    uint32_t a;
    asm("{ .reg .u64 t; cvta.to.shared.u64 t, %1; cvt.u32.u64 %0, t; }"
        : "=r"(a) : "l"(p));
    return a;
}

__device__ __forceinline__ void cp16(uint32_t saddr, const void* g) {
    asm volatile("cp.async.cg.shared.global [%0], [%1], 16;"
                 :: "r"(saddr), "l"(g) : "memory");
}
#define CP_COMMIT() asm volatile("cp.async.commit_group;" ::: "memory")
#define CP_WAIT(n)  asm volatile("cp.async.wait_group %0;" :: "n"(n) : "memory")

__device__ __forceinline__ void ldsm_x4(uint32_t* r, uint32_t addr) {
    asm volatile("ldmatrix.sync.aligned.m8n8.x4.shared.b16 {%0,%1,%2,%3}, [%4];"
                 : "=r"(r[0]), "=r"(r[1]), "=r"(r[2]), "=r"(r[3]) : "r"(addr));
}

__device__ __forceinline__ void mma_fp16(float* c, const uint32_t* a,
                                         uint32_t b0, uint32_t b1) {
    asm volatile(
        "mma.sync.aligned.m16n8k16.row.col.f32.f16.f16.f32 "
        "{%0,%1,%2,%3}, {%4,%5,%6,%7}, {%8,%9}, {%0,%1,%2,%3};"
        : "+f"(c[0]), "+f"(c[1]), "+f"(c[2]), "+f"(c[3])
        : "r"(a[0]), "r"(a[1]), "r"(a[2]), "r"(a[3]), "r"(b0), "r"(b1));
}

// Accurate fast tanh: tanh(x) = 1 - 2/(exp(2x)+1)
__device__ __forceinline__ float tanh_fast(float x) {
    float e = __expf(2.0f * x);
    return 1.0f - __fdividef(2.0f, e + 1.0f);
}

// ---------------------------------------------------------------------------
// Kernel 1: selector softmax + constant folding
// ---------------------------------------------------------------------------
__global__ __launch_bounds__(256)
void prep_selector_kernel(const float* __restrict__ leaf_logits,
                          float* __restrict__ wsel) {
    int idx = blockIdx.x * blockDim.x + threadIdx.x;   // w*8 + leaf
    if (idx >= WDIM * NLEAF) return;
    const float* lg = leaf_logits + (size_t)idx * NC;

    float m = lg[0];
    #pragma unroll
    for (int c = 1; c < NC; c++) m = fmaxf(m, lg[c]);

    float e[NC];
    float s = 0.0f;
    #pragma unroll
    for (int c = 0; c < NC; c++) { e[c] = __expf(lg[c] - m); s += e[c]; }
    float inv = 1.0f / s;

    float* o = wsel + (size_t)idx * 9;
    #pragma unroll
    for (int c = 0; c < SLOT; c++) o[c] = e[c] * inv;
    o[8] = (e[10] - e[8]) * inv;   // folded constants [-1, 0, 1]
}

// ---------------------------------------------------------------------------
// Kernel 2: slots = tanh(hidden @ slot_w + slot_b).  One warp per token.
// ---------------------------------------------------------------------------
__global__ __launch_bounds__(256)
void slots_kernel(const float* __restrict__ hidden,
                  const float* __restrict__ slot_w,
                  const float* __restrict__ slot_b,
                  float* __restrict__ slots) {
    int warp = (blockIdx.x * blockDim.x + threadIdx.x) >> 5;
    int lane = threadIdx.x & 31;
    if (warp >= NTOK) return;

    const float* h = hidden + (size_t)warp * DDIM;
    float acc[SLOT];
    #pragma unroll
    for (int s = 0; s < SLOT; s++) acc[s] = 0.0f;

    for (int j = lane; j < DDIM; j += 32) {
        float hv = h[j];
        float4 w0 = *reinterpret_cast<const float4*>(slot_w + (size_t)j * SLOT);
        float4 w1 = *reinterpret_cast<const float4*>(slot_w + (size_t)j * SLOT + 4);
        acc[0] = fmaf(hv, w0.x, acc[0]);
        acc[1] = fmaf(hv, w0.y, acc[1]);
        acc[2] = fmaf(hv, w0.z, acc[2]);
        acc[3] = fmaf(hv, w0.w, acc[3]);
        acc[4] = fmaf(hv, w1.x, acc[4]);
        acc[5] = fmaf(hv, w1.y, acc[5]);
        acc[6] = fmaf(hv, w1.z, acc[6]);
        acc[7] = fmaf(hv, w1.w, acc[7]);
    }
    #pragma unroll
    for (int off = 16; off > 0; off >>= 1) {
        #pragma unroll
        for (int s = 0; s < SLOT; s++)
            acc[s] += __shfl_down_sync(0xffffffffu, acc[s], off);
    }
    if (lane == 0) {
        #pragma unroll
        for (int s = 0; s < SLOT; s++)
            slots[(size_t)warp * SLOT + s] = tanh_fast(acc[s] + slot_b[s]);
    }
}

// ---------------------------------------------------------------------------
// Kernel 3: roots -> fp16, [token][w] = [M][K] row-major
// ---------------------------------------------------------------------------
__global__ __launch_bounds__(256)
void roots_kernel(const float* __restrict__ wsel,
                  const float* __restrict__ slots,
                  const float* __restrict__ np,
                  __half* __restrict__ A) {
    const int BT = 32, BW = 32;
    __shared__ float s_slots[BT][SLOT];
    __shared__ float s_wsel[BW][73];

    int tid = threadIdx.x;
    int t0 = blockIdx.y * BT;
    int w0 = blockIdx.x * BW;

    for (int i = tid; i < BW * 72; i += 256) {
        int r = i / 72, c = i % 72;
        s_wsel[r][c] = wsel[(size_t)(w0 + r) * 72 + c];
    }
    if (tid < BT * SLOT) {
        int r = tid / SLOT, c = tid % SLOT;
        s_slots[r][c] = slots[(size_t)(t0 + r) * SLOT + c];
    }
    __syncthreads();

    float lw = np[0], rw = np[1], pw = np[2], dw = np[3], nb = np[4];

    int tx = tid & 31;
    int ty = tid >> 5;
    #pragma unroll
    for (int i = 0; i < 4; i++) {
        int tl = ty * 4 + i;
        float v[NLEAF];
        #pragma unroll
        for (int l = 0; l < NLEAF; l++) {
            const float* wv = &s_wsel[tx][l * 9];
            float a = wv[8];
            #pragma unroll
            for (int c = 0; c < SLOT; c++)
                a = fmaf(wv[c], s_slots[tl][c], a);
            v[l] = a;
        }
        #pragma unroll
        for (int n = 4; n >= 1; n >>= 1) {
            #pragma unroll
            for (int j = 0; j < 4; j++) {
                if (j < n) {
                    float L = v[2 * j], R = v[2 * j + 1];
                    float z = fmaf(lw, L, nb);
                    z = fmaf(rw, R, z);
                    z = fmaf(pw * L, R, z);
                    z = fmaf(dw, L - R, z);
                    v[j] = tanh_fast(z);
                }
            }
        }
        A[(size_t)(t0 + tl) * WDIM + w0 + tx] = __float2half(v[0]);
    }
}

// ---------------------------------------------------------------------------
// Kernel 3b: transpose out_w [K][N] fp32 -> B [N][K] fp16
// ---------------------------------------------------------------------------
__global__ __launch_bounds__(256)
void transpose_kernel(const float* __restrict__ W,
                      __half* __restrict__ B) {
    __shared__ float t[32][33];
    int tx = threadIdx.x, ty = threadIdx.y;       // block (32, 8)
    int k0 = blockIdx.x * 32, n0 = blockIdx.y * 32;

    #pragma unroll
    for (int i = 0; i < 4; i++)
        t[ty + 8 * i][tx] = W[(size_t)(k0 + ty + 8 * i) * DDIM + n0 + tx];
    __syncthreads();

    #pragma unroll
    for (int i = 0; i < 4; i++)
        B[(size_t)(n0 + ty + 8 * i) * WDIM + k0 + tx] = __float2half(t[tx][ty + 8 * i]);
}

// ---------------------------------------------------------------------------
// Kernel 4: mma.sync fp16 GEMM.  C[4096,1024] = A B^T + bias  (fp32 accum)
// CTA 128x256, K-chunk 64, 3-stage cp.async pipeline, 16 warps (4x4).
// ---------------------------------------------------------------------------
__global__ void __launch_bounds__(GT, 1)
gemm_mma_kernel(const __half* __restrict__ A,
                const __half* __restrict__ B,
                const float* __restrict__ bias,
                float* __restrict__ C) {
    extern __shared__ char smem[];
    const uint32_t sbase = smem_u32(smem);
    const int tid  = threadIdx.x;
    const int lane = tid & 31;
    const int w    = tid >> 5;        // 0..15
    const int wm   = w & 3;           // M warp coord (x32)
    const int wn   = w >> 2;          // N warp coord (x64)
    const int brow = blockIdx.y * TMM;
    const int bcol = blockIdx.x * TNN;
    const int K = WDIM;

    float acc[2][8][4];
    #pragma unroll
    for (int a = 0; a < 2; a++)
        #pragma unroll
        for (int b = 0; b < 8; b++)
            #pragma unroll
            for (int c = 0; c < 4; c++) acc[a][b][c] = 0.0f;

    // ldmatrix lane->address precomputation
    const int lr   = lane & 7;
    const int ls8  = (lane >> 3) & 1;       // A: +8 rows    B: +1 k-chunk
    const int lhi  = lane >> 4;             // A: +1 k-chunk B: +8 rows
    const int arow0 = wm * 32 + lr + ls8 * 8;
    const int brow0 = wn * 64 + lr + lhi * 8;
    const uint32_t aswz = arow0 & 7;
    const uint32_t bswz = brow0 & 7;
    uint32_t arowb[2], browb[4];
    #pragma unroll
    for (int mt = 0; mt < 2; mt++) arowb[mt] = (uint32_t)(arow0 + mt * 16) << 7;
    #pragma unroll
    for (int i = 0; i < 4; i++)    browb[i] = (uint32_t)(brow0 + i * 16) << 7;

    // stage loader: A rows (brow..+127), B rows (bcol..+255), k0..k0+63
    auto load_stage = [&](int ci) {
        const uint32_t sb = sbase + (ci % NSTG) * STAGE;
        const int k0 = ci * KCC;
        #pragma unroll
        for (int it = 0; it < 2; it++) {
            int idx = tid + it * GT;          // 0..1023
            int r = idx >> 3, c = idx & 7;
            uint32_t sw = ((uint32_t)r << 7) + (((uint32_t)(c ^ (r & 7))) << 4);
            cp16(sb + OFF_A + sw, A + (size_t)(brow + r) * K + k0 + c * 8);
        }
        #pragma unroll
        for (int it = 0; it < 4; it++) {
            int idx = tid + it * GT;          // 0..2047
            int r = idx >> 3, c = idx & 7;
            uint32_t sw = ((uint32_t)r << 7) + (((uint32_t)(c ^ (r & 7))) << 4);
            cp16(sb + OFF_B + sw, B + (size_t)(bcol + r) * K + k0 + c * 8);
        }
    };

    load_stage(0); CP_COMMIT();
    load_stage(1); CP_COMMIT();

    for (int i = 0; i < NCH; i++) {
        CP_WAIT(1);            // stage i landed (this thread's view)
        __syncthreads();       // visible to all; all warps done with stage i-1

        if (i + 2 < NCH) { load_stage(i + 2); CP_COMMIT(); }

        const uint32_t sb = sbase + (i % NSTG) * STAGE;
        #pragma unroll
        for (int s = 0; s < 4; s++) {
            uint32_t ach = (((uint32_t)(2 * s + lhi)) ^ aswz) << 4;
            uint32_t bch = (((uint32_t)(2 * s + ls8)) ^ bswz) << 4;
            uint32_t af[2][4], bf[4][4];
            #pragma unroll
            for (int mt = 0; mt < 2; mt++)
                ldsm_x4(af[mt], sb + OFF_A + arowb[mt] + ach);
            #pragma unroll
            for (int bt = 0; bt < 4; bt++)
                ldsm_x4(bf[bt], sb + OFF_B + browb[bt] + bch);
            #pragma unroll
            for (int mt = 0; mt < 2; mt++)
                #pragma unroll
                for (int bt = 0; bt < 4; bt++) {
                    mma_fp16(acc[mt][2 * bt + 0], af[mt], bf[bt][0], bf[bt][1]);
                    mma_fp16(acc[mt][2 * bt + 1], af[mt], bf[bt][2], bf[bt][3]);
                }
        }
    }

    // Epilogue: acc -> C + bias
    const int r0 = lane >> 2;
    const int c0 = (lane & 3) * 2;
    #pragma unroll
    for (int mt = 0; mt < 2; mt++) {
        int grow = brow + wm * 32 + mt * 16 + r0;
        #pragma unroll
        for (int half = 0; half < 2; half++) {
            float* crow = C + (size_t)(grow + half * 8) * DDIM;
            #pragma unroll
            for (int nt = 0; nt < 8; nt++) {
                int gc = bcol + wn * 64 + nt * 8 + c0;
                float2 o;
                o.x = acc[mt][nt][half * 2 + 0] + bias[gc];
                o.y = acc[mt][nt][half * 2 + 1] + bias[gc + 1];
                *reinterpret_cast<float2*>(crow + gc) = o;
            }
        }
    }
}

// ---------------------------------------------------------------------------
// Launch.  Inputs: hidden, slot_w, slot_b, leaf_logits, node_params, out_w, out_b
// ---------------------------------------------------------------------------
extern "C" void kernel_launch(void* const* d_in, const int* in_sizes, int n_in,
                              void* d_out, int out_size) {
    const float* hidden      = (const float*)d_in[0];
    const float* slot_w      = (const float*)d_in[1];
    const float* slot_b      = (const float*)d_in[2];
    const float* leaf_logits = (const float*)d_in[3];
    const float* node_params = (const float*)d_in[4];
    const float* out_w       = (const float*)d_in[5];
    const float* out_b       = (const float*)d_in[6];
    float* out = (float*)d_out;

    float* wsel;  cudaGetSymbolAddress((void**)&wsel,  g_wsel);
    float* slots; cudaGetSymbolAddress((void**)&slots, g_slots);
    __half *A, *B;
    cudaGetSymbolAddress((void**)&A, g_a);
    cudaGetSymbolAddress((void**)&B, g_b);

    cudaFuncSetAttribute(gemm_mma_kernel,
                         cudaFuncAttributeMaxDynamicSharedMemorySize, GSMEM);

    // 1) selector softmax + constant folding
    prep_selector_kernel<<<(WDIM * NLEAF + 255) / 256, 256>>>(leaf_logits, wsel);

    // 2) slots
    slots_kernel<<<(NTOK * 32 + 255) / 256, 256>>>(hidden, slot_w, slot_b, slots);

    // 3b) transpose out_w -> fp16 [N][K]
    {
        dim3 grid(WDIM / 32, DDIM / 32);
        transpose_kernel<<<grid, dim3(32, 8)>>>(out_w, B);
    }

    // 3) roots -> fp16 [M][K]
    {
        dim3 grid(WDIM / 32, NTOK / 32);
        roots_kernel<<<grid, 256>>>(wsel, slots, node_params, A);
    }

    // 4) tensor-core GEMM + bias
    {
        dim3 grid(DDIM / TNN, NTOK / TMM);
        gemm_mma_kernel<<<grid, GT, GSMEM>>>(A, B, out_b, out);
    }
}

// round 5
// speedup vs baseline: 3.8030x; 1.0853x over previous
#include <cuda_runtime.h>
#include <cuda_bf16.h>
#include <cuda_fp16.h>
#include <cstdint>

// Problem constants (fixed shapes)
#define NTOK  4096      // B*S = 2*2048
#define DDIM  1024
#define WDIM  4096
#define SLOT  8
#define NLEAF 8         // 1 << TREE_DEPTH
#define NC    11        // SLOT + 3

// GEMM tiling: CTA 128(M) x 256(N), K-chunk 64, 512 threads (16 warps, 4x4)
#define TMM 128
#define TNN 256
#define KCC 64
#define GT  512
#define ABYTES (TMM * 128)            // 16 KB  (128 rows x 128B)
#define BBYTES (TNN * 128)            // 32 KB
#define OFF_A  0
#define OFF_B  (ABYTES)
#define STAGE  (ABYTES + BBYTES)      // 49152
#define NSTG   3
#define GSMEM  (NSTG * STAGE)         // 147456
#define NCH    (WDIM / KCC)           // 64

// Scratch (static device arrays — runtime alloc is forbidden)
__device__ __align__(128) float  g_wsel [WDIM * NLEAF * 12];  // 12-padded per leaf
__device__ __align__(128) float  g_slots[NTOK * SLOT];
__device__ __align__(128) __half g_a[(size_t)NTOK * WDIM];   // roots, fp16, [M][K]
__device__ __align__(128) __half g_b[(size_t)DDIM * WDIM];   // out_w^T, fp16, [N][K]

// ---------------------------------------------------------------------------
// PTX helpers (sm_80-era features only — no 'a'-suffix instructions)
// ---------------------------------------------------------------------------
__device__ __forceinline__ uint32_t smem_u32(const void* p) {
    uint32_t a;
    asm("{ .reg .u64 t; cvta.to.shared.u64 t, %1; cvt.u32.u64 %0, t; }"
        : "=r"(a) : "l"(p));
    return a;
}

__device__ __forceinline__ void cp16(uint32_t saddr, const void* g) {
    asm volatile("cp.async.cg.shared.global [%0], [%1], 16;"
                 :: "r"(saddr), "l"(g) : "memory");
}
#define CP_COMMIT() asm volatile("cp.async.commit_group;" ::: "memory")
#define CP_WAIT(n)  asm volatile("cp.async.wait_group %0;" :: "n"(n) : "memory")

__device__ __forceinline__ void ldsm_x4(uint32_t* r, uint32_t addr) {
    asm volatile("ldmatrix.sync.aligned.m8n8.x4.shared.b16 {%0,%1,%2,%3}, [%4];"
                 : "=r"(r[0]), "=r"(r[1]), "=r"(r[2]), "=r"(r[3]) : "r"(addr));
}

__device__ __forceinline__ void mma_fp16(float* c, const uint32_t* a,
                                         uint32_t b0, uint32_t b1) {
    asm volatile(
        "mma.sync.aligned.m16n8k16.row.col.f32.f16.f16.f32 "
        "{%0,%1,%2,%3}, {%4,%5,%6,%7}, {%8,%9}, {%0,%1,%2,%3};"
        : "+f"(c[0]), "+f"(c[1]), "+f"(c[2]), "+f"(c[3])
        : "r"(a[0]), "r"(a[1]), "r"(a[2]), "r"(a[3]), "r"(b0), "r"(b1));
}

// Accurate fast tanh: tanh(x) = 1 - 2/(exp(2x)+1)
__device__ __forceinline__ float tanh_fast(float x) {
    float e = __expf(2.0f * x);
    return 1.0f - __fdividef(2.0f, e + 1.0f);
}

// tanh from pre-scaled argument z' = 2*log2(e)*z : 4 instructions, 2 MUFU
__device__ __forceinline__ float tanh_prescaled(float zp) {
    float e, r;
    asm("ex2.approx.f32 %0, %1;" : "=f"(e) : "f"(zp));
    asm("rcp.approx.f32 %0, %1;" : "=f"(r) : "f"(e + 1.0f));
    return fmaf(-2.0f, r, 1.0f);
}

// ---------------------------------------------------------------------------
// Kernel 1: selector softmax + constant folding (12-padded output)
// ---------------------------------------------------------------------------
__global__ __launch_bounds__(256)
void prep_selector_kernel(const float* __restrict__ leaf_logits,
                          float* __restrict__ wsel) {
    int idx = blockIdx.x * blockDim.x + threadIdx.x;   // w*8 + leaf
    if (idx >= WDIM * NLEAF) return;
    const float* lg = leaf_logits + (size_t)idx * NC;

    float m = lg[0];
    #pragma unroll
    for (int c = 1; c < NC; c++) m = fmaxf(m, lg[c]);

    float e[NC];
    float s = 0.0f;
    #pragma unroll
    for (int c = 0; c < NC; c++) { e[c] = __expf(lg[c] - m); s += e[c]; }
    float inv = 1.0f / s;

    float* o = wsel + (size_t)idx * 12;
    #pragma unroll
    for (int c = 0; c < SLOT; c++) o[c] = e[c] * inv;
    o[8]  = (e[10] - e[8]) * inv;   // folded constants [-1, 0, 1]
    o[9]  = 0.0f;
    o[10] = 0.0f;
    o[11] = 0.0f;
}

// ---------------------------------------------------------------------------
// Kernel 2: slots = tanh(hidden @ slot_w + slot_b).  One warp per token.
// ---------------------------------------------------------------------------
__global__ __launch_bounds__(256)
void slots_kernel(const float* __restrict__ hidden,
                  const float* __restrict__ slot_w,
                  const float* __restrict__ slot_b,
                  float* __restrict__ slots) {
    int warp = (blockIdx.x * blockDim.x + threadIdx.x) >> 5;
    int lane = threadIdx.x & 31;
    if (warp >= NTOK) return;

    const float* h = hidden + (size_t)warp * DDIM;
    float acc[SLOT];
    #pragma unroll
    for (int s = 0; s < SLOT; s++) acc[s] = 0.0f;

    for (int j = lane; j < DDIM; j += 32) {
        float hv = h[j];
        float4 w0 = *reinterpret_cast<const float4*>(slot_w + (size_t)j * SLOT);
        float4 w1 = *reinterpret_cast<const float4*>(slot_w + (size_t)j * SLOT + 4);
        acc[0] = fmaf(hv, w0.x, acc[0]);
        acc[1] = fmaf(hv, w0.y, acc[1]);
        acc[2] = fmaf(hv, w0.z, acc[2]);
        acc[3] = fmaf(hv, w0.w, acc[3]);
        acc[4] = fmaf(hv, w1.x, acc[4]);
        acc[5] = fmaf(hv, w1.y, acc[5]);
        acc[6] = fmaf(hv, w1.z, acc[6]);
        acc[7] = fmaf(hv, w1.w, acc[7]);
    }
    #pragma unroll
    for (int off = 16; off > 0; off >>= 1) {
        #pragma unroll
        for (int s = 0; s < SLOT; s++)
            acc[s] += __shfl_down_sync(0xffffffffu, acc[s], off);
    }
    if (lane == 0) {
        #pragma unroll
        for (int s = 0; s < SLOT; s++)
            slots[(size_t)warp * SLOT + s] = tanh_fast(acc[s] + slot_b[s]);
    }
}

// ---------------------------------------------------------------------------
// Kernel 3: roots -> fp16, [token][w] = [M][K] row-major
// Tile 16 tokens x 32 w, 256 threads, 2 tokens per thread, leaf-outer.
// ---------------------------------------------------------------------------
#define RBT 16
#define WROW 100   // smem row stride (floats); 100 % 32 == 4 -> conflict-free LDS.128
__global__ __launch_bounds__(256)
void roots_kernel(const float* __restrict__ wsel,
                  const float* __restrict__ slots,
                  const float* __restrict__ np,
                  __half* __restrict__ A) {
    __shared__ float s_wsel[32 * WROW];
    __shared__ float s_slots[RBT * SLOT];

    int tid = threadIdx.x;
    int w0 = blockIdx.x * 32;
    int t0 = blockIdx.y * RBT;

    // load wsel tile: 32 rows x 96 floats = 768 float4
    {
        const float4* gw = reinterpret_cast<const float4*>(wsel + (size_t)w0 * 96);
        #pragma unroll
        for (int i = tid; i < 768; i += 256) {
            int r = i / 24, c = i % 24;
            *reinterpret_cast<float4*>(&s_wsel[r * WROW + c * 4]) = gw[r * 24 + c];
        }
    }
    // load slots tile: 16 tokens x 8 floats = 32 float4
    if (tid < RBT * SLOT / 4)
        reinterpret_cast<float4*>(s_slots)[tid] =
            reinterpret_cast<const float4*>(slots + (size_t)t0 * SLOT)[tid];
    __syncthreads();

    // node coefficients, pre-scaled by 2*log2(e) (folds tanh's exp scaling)
    const float SC = 2.8853900817779268f;
    const float a1  = (np[0] + np[3]) * SC;   // (lw + dw)
    const float a2  = (np[1] - np[3]) * SC;   // (rw - dw)
    const float pws = np[2] * SC;
    const float nbs = np[4] * SC;

    int tx = tid & 31;       // w within tile
    int ty = tid >> 5;       // 0..7 -> tokens ty*2, ty*2+1

    // slots for this thread's 2 tokens -> registers
    float sl[2][SLOT];
    #pragma unroll
    for (int t = 0; t < 2; t++) {
        float4 s0 = *reinterpret_cast<float4*>(&s_slots[(ty * 2 + t) * SLOT]);
        float4 s1 = *reinterpret_cast<float4*>(&s_slots[(ty * 2 + t) * SLOT + 4]);
        sl[t][0] = s0.x; sl[t][1] = s0.y; sl[t][2] = s0.z; sl[t][3] = s0.w;
        sl[t][4] = s1.x; sl[t][5] = s1.y; sl[t][6] = s1.z; sl[t][7] = s1.w;
    }

    // leaf values: load each leaf's 12 floats once, use for both tokens
    float v[2][NLEAF];
    #pragma unroll
    for (int l = 0; l < NLEAF; l++) {
        const float* wp = &s_wsel[tx * WROW + l * 12];
        float4 wv0 = *reinterpret_cast<const float4*>(wp);
        float4 wv1 = *reinterpret_cast<const float4*>(wp + 4);
        float4 wv2 = *reinterpret_cast<const float4*>(wp + 8);   // .x = bias
        #pragma unroll
        for (int t = 0; t < 2; t++) {
            float a = fmaf(wv0.x, sl[t][0], wv2.x);
            a = fmaf(wv0.y, sl[t][1], a);
            a = fmaf(wv0.z, sl[t][2], a);
            a = fmaf(wv0.w, sl[t][3], a);
            a = fmaf(wv1.x, sl[t][4], a);
            a = fmaf(wv1.y, sl[t][5], a);
            a = fmaf(wv1.z, sl[t][6], a);
            a = fmaf(wv1.w, sl[t][7], a);
            v[t][l] = a;
        }
    }

    // 3-level tree: node = tanh(a1*L + a2*R + pw*L*R + nb), arg pre-scaled
    #pragma unroll
    for (int t = 0; t < 2; t++) {
        #pragma unroll
        for (int n = 4; n >= 1; n >>= 1) {
            #pragma unroll
            for (int j = 0; j < 4; j++) {
                if (j < n) {
                    float L = v[t][2 * j], R = v[t][2 * j + 1];
                    float zp = fmaf(pws, L * R, nbs);
                    zp = fmaf(a2, R, zp);
                    zp = fmaf(a1, L, zp);
                    v[t][j] = tanh_prescaled(zp);
                }
            }
        }
        A[(size_t)(t0 + ty * 2 + t) * WDIM + w0 + tx] = __float2half(v[t][0]);
    }
}

// ---------------------------------------------------------------------------
// Kernel 3b: transpose out_w [K][N] fp32 -> B [N][K] fp16
// ---------------------------------------------------------------------------
__global__ __launch_bounds__(256)
void transpose_kernel(const float* __restrict__ W,
                      __half* __restrict__ B) {
    __shared__ float t[32][33];
    int tx = threadIdx.x, ty = threadIdx.y;       // block (32, 8)
    int k0 = blockIdx.x * 32, n0 = blockIdx.y * 32;

    #pragma unroll
    for (int i = 0; i < 4; i++)
        t[ty + 8 * i][tx] = W[(size_t)(k0 + ty + 8 * i) * DDIM + n0 + tx];
    __syncthreads();

    #pragma unroll
    for (int i = 0; i < 4; i++)
        B[(size_t)(n0 + ty + 8 * i) * WDIM + k0 + tx] = __float2half(t[tx][ty + 8 * i]);
}

// ---------------------------------------------------------------------------
// Kernel 4: mma.sync fp16 GEMM.  C[4096,1024] = A B^T + bias  (fp32 accum)
// CTA 128x256, K-chunk 64, 3-stage cp.async pipeline, 16 warps (4x4).
// ---------------------------------------------------------------------------
__global__ void __launch_bounds__(GT, 1)
gemm_mma_kernel(const __half* __restrict__ A,
                const __half* __restrict__ B,
                const float* __restrict__ bias,
                float* __restrict__ C) {
    extern __shared__ char smem[];
    const uint32_t sbase = smem_u32(smem);
    const int tid  = threadIdx.x;
    const int lane = tid & 31;
    const int w    = tid >> 5;        // 0..15
    const int wm   = w & 3;           // M warp coord (x32)
    const int wn   = w >> 2;          // N warp coord (x64)
    const int brow = blockIdx.y * TMM;
    const int bcol = blockIdx.x * TNN;
    const int K = WDIM;

    float acc[2][8][4];
    #pragma unroll
    for (int a = 0; a < 2; a++)
        #pragma unroll
        for (int b = 0; b < 8; b++)
            #pragma unroll
            for (int c = 0; c < 4; c++) acc[a][b][c] = 0.0f;

    // ldmatrix lane->address precomputation
    const int lr   = lane & 7;
    const int ls8  = (lane >> 3) & 1;       // A: +8 rows    B: +1 k-chunk
    const int lhi  = lane >> 4;             // A: +1 k-chunk B: +8 rows
    const int arow0 = wm * 32 + lr + ls8 * 8;
    const int brow0 = wn * 64 + lr + lhi * 8;
    const uint32_t aswz = arow0 & 7;
    const uint32_t bswz = brow0 & 7;
    uint32_t arowb[2], browb[4];
    #pragma unroll
    for (int mt = 0; mt < 2; mt++) arowb[mt] = (uint32_t)(arow0 + mt * 16) << 7;
    #pragma unroll
    for (int i = 0; i < 4; i++)    browb[i] = (uint32_t)(brow0 + i * 16) << 7;

    // stage loader: A rows (brow..+127), B rows (bcol..+255), k0..k0+63
    auto load_stage = [&](int ci) {
        const uint32_t sb = sbase + (ci % NSTG) * STAGE;
        const int k0 = ci * KCC;
        #pragma unroll
        for (int it = 0; it < 2; it++) {
            int idx = tid + it * GT;          // 0..1023
            int r = idx >> 3, c = idx & 7;
            uint32_t sw = ((uint32_t)r << 7) + (((uint32_t)(c ^ (r & 7))) << 4);
            cp16(sb + OFF_A + sw, A + (size_t)(brow + r) * K + k0 + c * 8);
        }
        #pragma unroll
        for (int it = 0; it < 4; it++) {
            int idx = tid + it * GT;          // 0..2047
            int r = idx >> 3, c = idx & 7;
            uint32_t sw = ((uint32_t)r << 7) + (((uint32_t)(c ^ (r & 7))) << 4);
            cp16(sb + OFF_B + sw, B + (size_t)(bcol + r) * K + k0 + c * 8);
        }
    };

    load_stage(0); CP_COMMIT();
    load_stage(1); CP_COMMIT();

    for (int i = 0; i < NCH; i++) {
        CP_WAIT(1);            // stage i landed (this thread's view)
        __syncthreads();       // visible to all; all warps done with stage i-1

        if (i + 2 < NCH) { load_stage(i + 2); CP_COMMIT(); }

        const uint32_t sb = sbase + (i % NSTG) * STAGE;
        #pragma unroll
        for (int s = 0; s < 4; s++) {
            uint32_t ach = (((uint32_t)(2 * s + lhi)) ^ aswz) << 4;
            uint32_t bch = (((uint32_t)(2 * s + ls8)) ^ bswz) << 4;
            uint32_t af[2][4], bf[4][4];
            #pragma unroll
            for (int mt = 0; mt < 2; mt++)
                ldsm_x4(af[mt], sb + OFF_A + arowb[mt] + ach);
            #pragma unroll
            for (int bt = 0; bt < 4; bt++)
                ldsm_x4(bf[bt], sb + OFF_B + browb[bt] + bch);
            #pragma unroll
            for (int mt = 0; mt < 2; mt++)
                #pragma unroll
                for (int bt = 0; bt < 4; bt++) {
                    mma_fp16(acc[mt][2 * bt + 0], af[mt], bf[bt][0], bf[bt][1]);
                    mma_fp16(acc[mt][2 * bt + 1], af[mt], bf[bt][2], bf[bt][3]);
                }
        }
    }

    // Epilogue: acc -> C + bias
    const int r0 = lane >> 2;
    const int c0 = (lane & 3) * 2;
    #pragma unroll
    for (int mt = 0; mt < 2; mt++) {
        int grow = brow + wm * 32 + mt * 16 + r0;
        #pragma unroll
        for (int half = 0; half < 2; half++) {
            float* crow = C + (size_t)(grow + half * 8) * DDIM;
            #pragma unroll
            for (int nt = 0; nt < 8; nt++) {
                int gc = bcol + wn * 64 + nt * 8 + c0;
                float2 o;
                o.x = acc[mt][nt][half * 2 + 0] + bias[gc];
                o.y = acc[mt][nt][half * 2 + 1] + bias[gc + 1];
                *reinterpret_cast<float2*>(crow + gc) = o;
            }
        }
    }
}

// ---------------------------------------------------------------------------
// Launch.  Inputs: hidden, slot_w, slot_b, leaf_logits, node_params, out_w, out_b
// ---------------------------------------------------------------------------
extern "C" void kernel_launch(void* const* d_in, const int* in_sizes, int n_in,
                              void* d_out, int out_size) {
    const float* hidden      = (const float*)d_in[0];
    const float* slot_w      = (const float*)d_in[1];
    const float* slot_b      = (const float*)d_in[2];
    const float* leaf_logits = (const float*)d_in[3];
    const float* node_params = (const float*)d_in[4];
    const float* out_w       = (const float*)d_in[5];
    const float* out_b       = (const float*)d_in[6];
    float* out = (float*)d_out;

    float* wsel;  cudaGetSymbolAddress((void**)&wsel,  g_wsel);
    float* slots; cudaGetSymbolAddress((void**)&slots, g_slots);
    __half *A, *B;
    cudaGetSymbolAddress((void**)&A, g_a);
    cudaGetSymbolAddress((void**)&B, g_b);

    cudaFuncSetAttribute(gemm_mma_kernel,
                         cudaFuncAttributeMaxDynamicSharedMemorySize, GSMEM);

    // 1) selector softmax + constant folding (12-padded)
    prep_selector_kernel<<<(WDIM * NLEAF + 255) / 256, 256>>>(leaf_logits, wsel);

    // 2) slots
    slots_kernel<<<(NTOK * 32 + 255) / 256, 256>>>(hidden, slot_w, slot_b, slots);

    // 3b) transpose out_w -> fp16 [N][K]
    {
        dim3 grid(WDIM / 32, DDIM / 32);
        transpose_kernel<<<grid, dim3(32, 8)>>>(out_w, B);
    }

    // 3) roots -> fp16 [M][K]
    {
        dim3 grid(WDIM / 32, NTOK / RBT);
        roots_kernel<<<grid, 256>>>(wsel, slots, node_params, A);
    }

    // 4) tensor-core GEMM + bias
    {
        dim3 grid(DDIM / TNN, NTOK / TMM);
        gemm_mma_kernel<<<grid, GT, GSMEM>>>(A, B, out_b, out);
    }
}